// round 3
// baseline (speedup 1.0000x reference)
#include <cuda_runtime.h>
#include <cuda_bf16.h>

// GCN: out = GCNConv(relu(GCNConv(x))), symmetric-normalized with self loops.
// CSR (dst-indexed) rebuilt every launch (determinism rule). Features pre-scaled
// by dis[src] in GEMM epilogue; aggregation is warp-per-node, register-
// accumulated, no float atomics; self loop handled algebraically.
//
// edge_index is int32 (JAX x64 disabled: jnp.int64 request silently yields
// int32) — reading it as int64 was the source of the round-1/2 address traps.

#define MAXN 100000
#define MAXE 1600000
#define D 64

__device__ __align__(16) int   g_indeg[MAXN];
__device__ __align__(16) int   g_rowptr[MAXN + 1];
__device__ __align__(16) int   g_cursor[MAXN];
__device__ __align__(16) int   g_col[MAXE];
__device__ __align__(16) float g_dis[MAXN];
__device__ __align__(16) int   g_excl[100352];
__device__ __align__(16) int   g_bsums[128];
__device__ __align__(16) int   g_boffs[128];
__device__ __align__(16) float g_G[MAXN * D];  // pre-scaled features for agg
__device__ __align__(16) float g_H[MAXN * D];  // relu output of layer 1

// ---------------------------------------------------------------- degree
__global__ void k_zero(int* __restrict__ indeg, int N) {
    int i = blockIdx.x * blockDim.x + threadIdx.x;
    if (i < N) indeg[i] = 0;
}

__global__ void k_count(const int* __restrict__ dst,
                        int* __restrict__ indeg, int E, int N) {
    int e = blockIdx.x * blockDim.x + threadIdx.x;
    if (e < E) {
        int d = dst[e];
        if (d >= 0 && d < N) atomicAdd(&indeg[d], 1);
    }
}

// ------------------------------------------------------------ prefix scan
// chunk of 1024 per block (256 thr x 4 items), exclusive within chunk
__global__ void k_scan1(const int* __restrict__ indeg, int* __restrict__ excl,
                        int* __restrict__ bsums, int N) {
    __shared__ int s[256];
    int tid = threadIdx.x;
    int base = blockIdx.x * 1024;
    int v[4];
    int sum = 0;
#pragma unroll
    for (int i = 0; i < 4; i++) {
        int idx = base + tid * 4 + i;
        int x = (idx < N) ? indeg[idx] : 0;
        v[i] = sum;
        sum += x;
    }
    s[tid] = sum;
    __syncthreads();
    for (int off = 1; off < 256; off <<= 1) {
        int t = 0;
        if (tid >= off) t = s[tid - off];
        __syncthreads();
        s[tid] += t;
        __syncthreads();
    }
    int thr_off = s[tid] - sum;
#pragma unroll
    for (int i = 0; i < 4; i++) {
        int idx = base + tid * 4 + i;
        if (idx < N) excl[idx] = thr_off + v[i];
    }
    if (tid == 255) bsums[blockIdx.x] = s[255];
}

__global__ void k_scan2(const int* __restrict__ bsums,
                        int* __restrict__ boffs, int nb) {
    __shared__ int s[128];
    int tid = threadIdx.x;
    int x = (tid < nb) ? bsums[tid] : 0;
    s[tid] = x;
    __syncthreads();
    for (int off = 1; off < 128; off <<= 1) {
        int t = 0;
        if (tid >= off) t = s[tid - off];
        __syncthreads();
        s[tid] += t;
        __syncthreads();
    }
    if (tid < nb) boffs[tid] = s[tid] - x;  // exclusive
}

__global__ void k_scan3(const int* __restrict__ indeg,
                        const int* __restrict__ excl,
                        const int* __restrict__ boffs,
                        int* __restrict__ rowptr, int* __restrict__ cursor,
                        float* __restrict__ dis, int N, int E) {
    int i = blockIdx.x * blockDim.x + threadIdx.x;
    if (i < N) {
        int e = excl[i] + boffs[i >> 10];
        rowptr[i] = e;
        cursor[i] = e;
        dis[i] = rsqrtf((float)(indeg[i] + 1));  // +1 self loop
    }
    if (i == 0) rowptr[N] = E;
}

__global__ void k_fill(const int* __restrict__ src,
                       const int* __restrict__ dst,
                       int* __restrict__ cursor, int* __restrict__ col,
                       int E, int N) {
    int e = blockIdx.x * blockDim.x + threadIdx.x;
    if (e < E) {
        int d = dst[e];
        if (d >= 0 && d < N) {
            int pos = atomicAdd(&cursor[d], 1);
            col[pos] = src[e];
        }
    }
}

// ------------------------------------------------------------------ GEMM
// G[n,j] = dis[n] * sum_k X[n,k] * W[j,k]   (W row-major [64 out][64 in])
__global__ void k_gemm(const float* __restrict__ X, const float* __restrict__ W,
                       const float* __restrict__ dis, float* __restrict__ G,
                       int N) {
    __shared__ float Wt[64][65];  // transposed, padded
    __shared__ float Xs[32][64];
    int tid = threadIdx.x;  // 256
    for (int i = tid; i < 4096; i += 256) {
        Wt[i & 63][i >> 6] = W[i];
    }
    int base = blockIdx.x * 32;
    for (int i = tid; i < 2048; i += 256) {
        int n = base + (i >> 6);
        Xs[i >> 6][i & 63] = (n < N) ? X[n * D + (i & 63)] : 0.f;
    }
    __syncthreads();
    int j = tid & 63;
    for (int r = tid >> 6; r < 32; r += 4) {
        int n = base + r;
        if (n < N) {
            float acc = 0.f;
#pragma unroll
            for (int k = 0; k < 64; k++) acc = fmaf(Xs[r][k], Wt[k][j], acc);
            G[n * D + j] = acc * dis[n];
        }
    }
}

// ------------------------------------------------------------- aggregate
// warp per dst node, lane handles a float2 of features.
// out[d] = dis[d]*(sum_{s in in(d)} g[s] + g[d]) + b   (relu when do_relu)
__global__ void k_agg(const int* __restrict__ rowptr,
                      const int* __restrict__ col,
                      const float* __restrict__ G,
                      const float* __restrict__ dis,
                      const float* __restrict__ bias,
                      float* __restrict__ outp, int do_relu, int N) {
    int node = (blockIdx.x * blockDim.x + threadIdx.x) >> 5;
    int lane = threadIdx.x & 31;
    if (node >= N) return;
    const float2* G2 = (const float2*)G;
    int s0 = rowptr[node];
    int s1 = rowptr[node + 1];
    float2 self = G2[node * 32 + lane];  // self-loop term
    float ax = self.x, ay = self.y;
    int j = s0;
    for (; j + 3 < s1; j += 4) {
        int c0 = col[j], c1 = col[j + 1], c2 = col[j + 2], c3 = col[j + 3];
        float2 v0 = G2[c0 * 32 + lane];
        float2 v1 = G2[c1 * 32 + lane];
        float2 v2 = G2[c2 * 32 + lane];
        float2 v3 = G2[c3 * 32 + lane];
        ax += v0.x + v1.x + v2.x + v3.x;
        ay += v0.y + v1.y + v2.y + v3.y;
    }
    for (; j < s1; j++) {
        float2 v = G2[col[j] * 32 + lane];
        ax += v.x;
        ay += v.y;
    }
    float dsc = dis[node];
    const float2* b2 = (const float2*)bias;
    float2 b = b2[lane];
    float ox = fmaf(ax, dsc, b.x);
    float oy = fmaf(ay, dsc, b.y);
    if (do_relu) {
        ox = fmaxf(ox, 0.f);
        oy = fmaxf(oy, 0.f);
    }
    float2* O2 = (float2*)outp;
    O2[node * 32 + lane] = make_float2(ox, oy);
}

// ----------------------------------------------------------------- launch
extern "C" void kernel_launch(void* const* d_in, const int* in_sizes, int n_in,
                              void* d_out, int out_size) {
    const float* x  = (const float*)d_in[0];
    const int*   ei = (const int*)d_in[1];   // int32! (JAX x64 disabled)
    const float* W1 = (const float*)d_in[2];
    const float* b1 = (const float*)d_in[3];
    const float* W2 = (const float*)d_in[4];
    const float* b2 = (const float*)d_in[5];
    float* out = (float*)d_out;

    int N = in_sizes[0] / D;
    int E = in_sizes[1] / 2;
    if (N > MAXN) N = MAXN;
    if (E > MAXE) E = MAXE;
    const int* src = ei;
    const int* dst = ei + E;

    void *p_indeg, *p_rowptr, *p_cursor, *p_col, *p_dis, *p_excl, *p_bsums,
        *p_boffs, *p_G, *p_H;
    cudaGetSymbolAddress(&p_indeg, g_indeg);
    cudaGetSymbolAddress(&p_rowptr, g_rowptr);
    cudaGetSymbolAddress(&p_cursor, g_cursor);
    cudaGetSymbolAddress(&p_col, g_col);
    cudaGetSymbolAddress(&p_dis, g_dis);
    cudaGetSymbolAddress(&p_excl, g_excl);
    cudaGetSymbolAddress(&p_bsums, g_bsums);
    cudaGetSymbolAddress(&p_boffs, g_boffs);
    cudaGetSymbolAddress(&p_G, g_G);
    cudaGetSymbolAddress(&p_H, g_H);
    int*   indeg  = (int*)p_indeg;
    int*   rowptr = (int*)p_rowptr;
    int*   cursor = (int*)p_cursor;
    int*   col    = (int*)p_col;
    float* dis    = (float*)p_dis;
    int*   excl   = (int*)p_excl;
    int*   bsums  = (int*)p_bsums;
    int*   boffs  = (int*)p_boffs;
    float* G      = (float*)p_G;
    float* H      = (float*)p_H;

    int nb = (N + 255) / 256;
    int eb = (E + 255) / 256;
    int sb = (N + 1023) / 1024;
    int gb = (N + 31) / 32;
    int ab = (N + 7) / 8;  // 8 warps (nodes) per 256-thread block

    k_zero<<<nb, 256>>>(indeg, N);
    k_count<<<eb, 256>>>(dst, indeg, E, N);
    k_scan1<<<sb, 256>>>(indeg, excl, bsums, N);
    k_scan2<<<1, 128>>>(bsums, boffs, sb);
    k_scan3<<<nb, 256>>>(indeg, excl, boffs, rowptr, cursor, dis, N, E);
    k_fill<<<eb, 256>>>(src, dst, cursor, col, E, N);

    k_gemm<<<gb, 256>>>(x, W1, dis, G, N);
    k_agg<<<ab, 256>>>(rowptr, col, G, dis, b1, H, 1, N);
    k_gemm<<<gb, 256>>>(H, W2, dis, G, N);
    k_agg<<<ab, 256>>>(rowptr, col, G, dis, b2, out, 0, N);
}

// round 4
// speedup vs baseline: 1.0042x; 1.0042x over previous
#include <cuda_runtime.h>
#include <cuda_bf16.h>
#include <cuda_fp16.h>

// GCN: out = GCNConv(relu(GCNConv(x))), symmetric normalization + self loops.
// CSR (dst-indexed) rebuilt per launch; dis folded into GEMM epilogue;
// G stored fp16 (agg gather payload halved), fp32 accumulation;
// warp-per-node aggregation, no float atomics.
// indeg is re-zeroed by the LAST kernel so the next launch can skip k_zero
// (globals are zero-initialized at module load; invariant restored per launch).

#define MAXN 100000
#define MAXE 1600000
#define D 64

__device__ __align__(16) int    g_indeg[MAXN];
__device__ __align__(16) int    g_rowptr[MAXN + 1];
__device__ __align__(16) int    g_cursor[MAXN];
__device__ __align__(16) int    g_col[MAXE];
__device__ __align__(16) float  g_dis[MAXN];
__device__ __align__(16) int    g_excl[100352];
__device__ __align__(16) int    g_bsums[128];
__device__ __align__(16) __half g_G[MAXN * D];  // fp16 pre-scaled features
__device__ __align__(16) float  g_H[MAXN * D];  // relu output of layer 1

// ---------------------------------------------------------------- degree
__global__ void k_count(const int* __restrict__ dst,
                        int* __restrict__ indeg, int E, int N) {
    int e = blockIdx.x * blockDim.x + threadIdx.x;
    if (e < E) {
        int d = dst[e];
        if (d >= 0 && d < N) atomicAdd(&indeg[d], 1);
    }
}

// ------------------------------------------------------------ prefix scan
// chunk of 1024 per block (256 thr x 4 items), exclusive within chunk
__global__ void k_scan1(const int* __restrict__ indeg, int* __restrict__ excl,
                        int* __restrict__ bsums, int N) {
    __shared__ int s[256];
    int tid = threadIdx.x;
    int base = blockIdx.x * 1024;
    int v[4];
    int sum = 0;
#pragma unroll
    for (int i = 0; i < 4; i++) {
        int idx = base + tid * 4 + i;
        int x = (idx < N) ? indeg[idx] : 0;
        v[i] = sum;
        sum += x;
    }
    s[tid] = sum;
    __syncthreads();
    for (int off = 1; off < 256; off <<= 1) {
        int t = 0;
        if (tid >= off) t = s[tid - off];
        __syncthreads();
        s[tid] += t;
        __syncthreads();
    }
    int thr_off = s[tid] - sum;
#pragma unroll
    for (int i = 0; i < 4; i++) {
        int idx = base + tid * 4 + i;
        if (idx < N) excl[idx] = thr_off + v[i];
    }
    if (tid == 255) bsums[blockIdx.x] = s[255];
}

// scan3': each block (256 nodes, all inside one 1024-chunk) redundantly scans
// the <=128 chunk sums in smem, then emits rowptr/cursor/dis.
__global__ void k_scan3(const int* __restrict__ indeg,
                        const int* __restrict__ excl,
                        const int* __restrict__ bsums,
                        int* __restrict__ rowptr, int* __restrict__ cursor,
                        float* __restrict__ dis, int nb, int N, int E) {
    __shared__ int s[128];
    int tid = threadIdx.x;
    if (tid < 128) {
        s[tid] = (tid < nb) ? bsums[tid] : 0;
    }
    __syncthreads();
    for (int off = 1; off < 128; off <<= 1) {
        int t = 0;
        if (tid < 128 && tid >= off) t = s[tid - off];
        __syncthreads();
        if (tid < 128) s[tid] += t;
        __syncthreads();
    }
    int chunk = (blockIdx.x * 256) >> 10;           // same for whole block
    int boff = (chunk > 0) ? s[chunk - 1] : 0;      // exclusive chunk offset
    int i = blockIdx.x * 256 + tid;
    if (i < N) {
        int e = excl[i] + boff;
        rowptr[i] = e;
        cursor[i] = e;
        dis[i] = rsqrtf((float)(indeg[i] + 1));     // +1 self loop
    }
    if (i == 0) rowptr[N] = E;
}

__global__ void k_fill(const int* __restrict__ src,
                       const int* __restrict__ dst,
                       int* __restrict__ cursor, int* __restrict__ col,
                       int E, int N) {
    int e = blockIdx.x * blockDim.x + threadIdx.x;
    if (e < E) {
        int d = dst[e];
        if (d >= 0 && d < N) {
            int pos = atomicAdd(&cursor[d], 1);
            col[pos] = src[e];
        }
    }
}

// ------------------------------------------------------------------ GEMM
// G[n,j] = half( dis[n] * sum_k X[n,k] * W[j,k] )   (W row-major [out][in])
__global__ void k_gemm(const float* __restrict__ X, const float* __restrict__ W,
                       const float* __restrict__ dis, __half* __restrict__ G,
                       int N) {
    __shared__ float Wt[64][65];  // transposed, padded
    __shared__ float Xs[32][64];
    int tid = threadIdx.x;  // 256
    for (int i = tid; i < 4096; i += 256) {
        Wt[i & 63][i >> 6] = W[i];
    }
    int base = blockIdx.x * 32;
    for (int i = tid; i < 2048; i += 256) {
        int n = base + (i >> 6);
        Xs[i >> 6][i & 63] = (n < N) ? X[n * D + (i & 63)] : 0.f;
    }
    __syncthreads();
    int j = tid & 63;
    for (int r = tid >> 6; r < 32; r += 4) {
        int n = base + r;
        if (n < N) {
            float acc = 0.f;
#pragma unroll
            for (int k = 0; k < 64; k++) acc = fmaf(Xs[r][k], Wt[k][j], acc);
            G[n * D + j] = __float2half_rn(acc * dis[n]);
        }
    }
}

// ------------------------------------------------------------- aggregate
// warp per dst node, lane handles a half2 (2 features); fp32 accumulators.
// out[d] = dis[d]*(sum_{s in in(d)} g[s] + g[d]) + b   (relu when do_relu)
// reset_indeg != nullptr => also zero indeg[node] for the next launch.
__global__ void k_agg(const int* __restrict__ rowptr,
                      const int* __restrict__ col,
                      const __half* __restrict__ G,
                      const float* __restrict__ dis,
                      const float* __restrict__ bias,
                      float* __restrict__ outp, int do_relu,
                      int* reset_indeg, int N) {
    int node = (blockIdx.x * blockDim.x + threadIdx.x) >> 5;
    int lane = threadIdx.x & 31;
    if (node >= N) return;
    const __half2* G2 = (const __half2*)G;
    int s0 = rowptr[node];
    int s1 = rowptr[node + 1];
    float2 self = __half22float2(G2[node * 32 + lane]);  // self-loop term
    float a0x = self.x, a0y = self.y;
    float a1x = 0.f, a1y = 0.f, a2x = 0.f, a2y = 0.f, a3x = 0.f, a3y = 0.f;
    int j = s0;
    for (; j + 3 < s1; j += 4) {
        int c0 = col[j], c1 = col[j + 1], c2 = col[j + 2], c3 = col[j + 3];
        float2 v0 = __half22float2(G2[c0 * 32 + lane]);
        float2 v1 = __half22float2(G2[c1 * 32 + lane]);
        float2 v2 = __half22float2(G2[c2 * 32 + lane]);
        float2 v3 = __half22float2(G2[c3 * 32 + lane]);
        a0x += v0.x; a0y += v0.y;
        a1x += v1.x; a1y += v1.y;
        a2x += v2.x; a2y += v2.y;
        a3x += v3.x; a3y += v3.y;
    }
    for (; j < s1; j++) {
        float2 v = __half22float2(G2[col[j] * 32 + lane]);
        a0x += v.x; a0y += v.y;
    }
    float ax = (a0x + a1x) + (a2x + a3x);
    float ay = (a0y + a1y) + (a2y + a3y);
    float dsc = dis[node];
    const float2* b2 = (const float2*)bias;
    float2 b = b2[lane];
    float ox = fmaf(ax, dsc, b.x);
    float oy = fmaf(ay, dsc, b.y);
    if (do_relu) {
        ox = fmaxf(ox, 0.f);
        oy = fmaxf(oy, 0.f);
    }
    float2* O2 = (float2*)outp;
    O2[node * 32 + lane] = make_float2(ox, oy);
    if (reset_indeg && lane == 0) reset_indeg[node] = 0;  // ready next launch
}

// ----------------------------------------------------------------- launch
extern "C" void kernel_launch(void* const* d_in, const int* in_sizes, int n_in,
                              void* d_out, int out_size) {
    const float* x  = (const float*)d_in[0];
    const int*   ei = (const int*)d_in[1];   // int32 (JAX x64 disabled)
    const float* W1 = (const float*)d_in[2];
    const float* b1 = (const float*)d_in[3];
    const float* W2 = (const float*)d_in[4];
    const float* b2 = (const float*)d_in[5];
    float* out = (float*)d_out;

    int N = in_sizes[0] / D;
    int E = in_sizes[1] / 2;
    if (N > MAXN) N = MAXN;
    if (E > MAXE) E = MAXE;
    const int* src = ei;
    const int* dst = ei + E;

    void *p_indeg, *p_rowptr, *p_cursor, *p_col, *p_dis, *p_excl, *p_bsums,
        *p_G, *p_H;
    cudaGetSymbolAddress(&p_indeg, g_indeg);
    cudaGetSymbolAddress(&p_rowptr, g_rowptr);
    cudaGetSymbolAddress(&p_cursor, g_cursor);
    cudaGetSymbolAddress(&p_col, g_col);
    cudaGetSymbolAddress(&p_dis, g_dis);
    cudaGetSymbolAddress(&p_excl, g_excl);
    cudaGetSymbolAddress(&p_bsums, g_bsums);
    cudaGetSymbolAddress(&p_G, g_G);
    cudaGetSymbolAddress(&p_H, g_H);
    int*    indeg  = (int*)p_indeg;
    int*    rowptr = (int*)p_rowptr;
    int*    cursor = (int*)p_cursor;
    int*    col    = (int*)p_col;
    float*  dis    = (float*)p_dis;
    int*    excl   = (int*)p_excl;
    int*    bsums  = (int*)p_bsums;
    __half* G      = (__half*)p_G;
    float*  H      = (float*)p_H;

    int nb = (N + 255) / 256;
    int eb = (E + 255) / 256;
    int sb = (N + 1023) / 1024;
    int gb = (N + 31) / 32;
    int ab = (N + 7) / 8;  // 8 warps (nodes) per 256-thread block

    // indeg is zero on entry (zero-init at load; re-zeroed by agg2 each launch)
    k_count<<<eb, 256>>>(dst, indeg, E, N);
    k_scan1<<<sb, 256>>>(indeg, excl, bsums, N);
    k_scan3<<<nb, 256>>>(indeg, excl, bsums, rowptr, cursor, dis, sb, N, E);
    k_fill<<<eb, 256>>>(src, dst, cursor, col, E, N);

    k_gemm<<<gb, 256>>>(x, W1, dis, G, N);
    k_agg<<<ab, 256>>>(rowptr, col, G, dis, b1, H, 1, nullptr, N);   // 6th launch
    k_gemm<<<gb, 256>>>(H, W2, dis, G, N);
    k_agg<<<ab, 256>>>(rowptr, col, G, dis, b2, out, 0, indeg, N);
}

// round 5
// speedup vs baseline: 1.5695x; 1.5630x over previous
#include <cuda_runtime.h>
#include <cuda_bf16.h>
#include <cuda_fp16.h>

// GCN: out = GCNConv(relu(GCNConv(x))), symmetric normalization + self loops.
// CSR (dst-indexed) rebuilt per launch; dis folded into GEMM epilogue;
// G stored fp16; fp32 accumulation; no float atomics.
// R5: register-tiled GEMM (64x64 tile, 4x4/thread, swizzled W in smem);
//     agg with 4 nodes/warp, 8 lanes/node, uint4 (8xfp16) gathers.

#define MAXN 100000
#define MAXE 1600000
#define D 64

__device__ __align__(16) int    g_indeg[MAXN];
__device__ __align__(16) int    g_rowptr[MAXN + 1];
__device__ __align__(16) int    g_cursor[MAXN];
__device__ __align__(16) int    g_col[MAXE];
__device__ __align__(16) float  g_dis[MAXN];
__device__ __align__(16) int    g_excl[100352];
__device__ __align__(16) int    g_bsums[128];
__device__ __align__(16) __half g_G[MAXN * D];  // fp16 pre-scaled features
__device__ __align__(16) float  g_H[MAXN * D];  // relu output of layer 1

// ---------------------------------------------------------------- degree
__global__ void k_count(const int* __restrict__ dst,
                        int* __restrict__ indeg, int E, int N) {
    int e = blockIdx.x * blockDim.x + threadIdx.x;
    if (e < E) {
        int d = dst[e];
        if (d >= 0 && d < N) atomicAdd(&indeg[d], 1);
    }
}

// ------------------------------------------------------------ prefix scan
__global__ void k_scan1(const int* __restrict__ indeg, int* __restrict__ excl,
                        int* __restrict__ bsums, int N) {
    __shared__ int s[256];
    int tid = threadIdx.x;
    int base = blockIdx.x * 1024;
    int v[4];
    int sum = 0;
#pragma unroll
    for (int i = 0; i < 4; i++) {
        int idx = base + tid * 4 + i;
        int x = (idx < N) ? indeg[idx] : 0;
        v[i] = sum;
        sum += x;
    }
    s[tid] = sum;
    __syncthreads();
    for (int off = 1; off < 256; off <<= 1) {
        int t = 0;
        if (tid >= off) t = s[tid - off];
        __syncthreads();
        s[tid] += t;
        __syncthreads();
    }
    int thr_off = s[tid] - sum;
#pragma unroll
    for (int i = 0; i < 4; i++) {
        int idx = base + tid * 4 + i;
        if (idx < N) excl[idx] = thr_off + v[i];
    }
    if (tid == 255) bsums[blockIdx.x] = s[255];
}

// each block (256 nodes) redundantly scans the <=128 chunk sums in smem
__global__ void k_scan3(const int* __restrict__ indeg,
                        const int* __restrict__ excl,
                        const int* __restrict__ bsums,
                        int* __restrict__ rowptr, int* __restrict__ cursor,
                        float* __restrict__ dis, int nb, int N, int E) {
    __shared__ int s[128];
    int tid = threadIdx.x;
    if (tid < 128) s[tid] = (tid < nb) ? bsums[tid] : 0;
    __syncthreads();
    for (int off = 1; off < 128; off <<= 1) {
        int t = 0;
        if (tid < 128 && tid >= off) t = s[tid - off];
        __syncthreads();
        if (tid < 128) s[tid] += t;
        __syncthreads();
    }
    int chunk = (blockIdx.x * 256) >> 10;
    int boff = (chunk > 0) ? s[chunk - 1] : 0;
    int i = blockIdx.x * 256 + tid;
    if (i < N) {
        int e = excl[i] + boff;
        rowptr[i] = e;
        cursor[i] = e;
        dis[i] = rsqrtf((float)(indeg[i] + 1));  // +1 self loop
    }
    if (i == 0) rowptr[N] = E;
}

__global__ void k_fill(const int* __restrict__ src,
                       const int* __restrict__ dst,
                       int* __restrict__ cursor, int* __restrict__ col,
                       int E, int N) {
    int e = blockIdx.x * blockDim.x + threadIdx.x;
    if (e < E) {
        int d = dst[e];
        if (d >= 0 && d < N) {
            int pos = atomicAdd(&cursor[d], 1);
            col[pos] = src[e];
        }
    }
}

// ------------------------------------------------------------------ GEMM
// G[n,j] = half( dis[n] * sum_k X[n,k] * W[j,k] ), W row-major [out][in].
// 64x64 tile / block, 256 threads, 4x4 register tile per thread.
// Wt: [k][j] with XOR-swizzled float4 slots (conflict-light store,
// conflict-free vector reads). Xs: row-major (broadcast scalar reads).
__global__ void k_gemm(const float* __restrict__ X, const float* __restrict__ W,
                       const float* __restrict__ dis, __half* __restrict__ G,
                       int N) {
    __shared__ float Xs[64][64];
    __shared__ float Wt[64][64];
    int tid = threadIdx.x;
    int base = blockIdx.x * 64;

    for (int idx = tid; idx < 4096; idx += 256) {
        int r = idx >> 6, k = idx & 63;
        int n = base + r;
        Xs[r][k] = (n < N) ? X[n * D + k] : 0.f;
    }
    for (int idx = tid; idx < 4096; idx += 256) {
        int j = idx >> 6, k = idx & 63;
        float v = W[idx];
        int slot = (j >> 2) ^ (k & 15);
        Wt[k][slot * 4 + (j & 3)] = v;
    }
    __syncthreads();

    int c4 = (tid & 15) * 4;
    int r4 = (tid >> 4) * 4;
    int cslot = c4 >> 2;
    float acc[4][4];
#pragma unroll
    for (int i = 0; i < 4; i++)
#pragma unroll
        for (int q = 0; q < 4; q++) acc[i][q] = 0.f;

#pragma unroll 16
    for (int k = 0; k < 64; k++) {
        float4 wv = *(const float4*)&Wt[k][(cslot ^ (k & 15)) * 4];
        float x0 = Xs[r4 + 0][k];
        float x1 = Xs[r4 + 1][k];
        float x2 = Xs[r4 + 2][k];
        float x3 = Xs[r4 + 3][k];
        acc[0][0] = fmaf(x0, wv.x, acc[0][0]);
        acc[0][1] = fmaf(x0, wv.y, acc[0][1]);
        acc[0][2] = fmaf(x0, wv.z, acc[0][2]);
        acc[0][3] = fmaf(x0, wv.w, acc[0][3]);
        acc[1][0] = fmaf(x1, wv.x, acc[1][0]);
        acc[1][1] = fmaf(x1, wv.y, acc[1][1]);
        acc[1][2] = fmaf(x1, wv.z, acc[1][2]);
        acc[1][3] = fmaf(x1, wv.w, acc[1][3]);
        acc[2][0] = fmaf(x2, wv.x, acc[2][0]);
        acc[2][1] = fmaf(x2, wv.y, acc[2][1]);
        acc[2][2] = fmaf(x2, wv.z, acc[2][2]);
        acc[2][3] = fmaf(x2, wv.w, acc[2][3]);
        acc[3][0] = fmaf(x3, wv.x, acc[3][0]);
        acc[3][1] = fmaf(x3, wv.y, acc[3][1]);
        acc[3][2] = fmaf(x3, wv.z, acc[3][2]);
        acc[3][3] = fmaf(x3, wv.w, acc[3][3]);
    }

#pragma unroll
    for (int i = 0; i < 4; i++) {
        int n = base + r4 + i;
        if (n < N) {
            float d = dis[n];
            __half2 h01 = __floats2half2_rn(acc[i][0] * d, acc[i][1] * d);
            __half2 h23 = __floats2half2_rn(acc[i][2] * d, acc[i][3] * d);
            uint2 uu;
            uu.x = *reinterpret_cast<unsigned*>(&h01);
            uu.y = *reinterpret_cast<unsigned*>(&h23);
            *(uint2*)(G + n * D + c4) = uu;
        }
    }
}

// ------------------------------------------------------------- aggregate
// 4 nodes per warp, 8 lanes per node; each lane owns 8 fp16 features (16B).
// out[d] = dis[d]*(sum_{s in in(d)} g[s] + g[d]) + b   (relu when do_relu)
__device__ __forceinline__ void acc8(float* a, uint4 v) {
    __half2 h0 = *reinterpret_cast<__half2*>(&v.x);
    __half2 h1 = *reinterpret_cast<__half2*>(&v.y);
    __half2 h2 = *reinterpret_cast<__half2*>(&v.z);
    __half2 h3 = *reinterpret_cast<__half2*>(&v.w);
    float2 f0 = __half22float2(h0);
    float2 f1 = __half22float2(h1);
    float2 f2 = __half22float2(h2);
    float2 f3 = __half22float2(h3);
    a[0] += f0.x; a[1] += f0.y;
    a[2] += f1.x; a[3] += f1.y;
    a[4] += f2.x; a[5] += f2.y;
    a[6] += f3.x; a[7] += f3.y;
}

__global__ void k_agg(const int* __restrict__ rowptr,
                      const int* __restrict__ col,
                      const __half* __restrict__ G,
                      const float* __restrict__ dis,
                      const float* __restrict__ bias,
                      float* __restrict__ outp, int do_relu,
                      int* reset_indeg, int N) {
    int gw = (blockIdx.x * blockDim.x + threadIdx.x) >> 5;
    int lane = threadIdx.x & 31;
    int node = gw * 4 + (lane >> 3);
    int sub = lane & 7;
    bool valid = node < N;
    int s0 = 0, s1 = 0;
    if (valid) {
        s0 = rowptr[node];
        s1 = rowptr[node + 1];
    }
    float a[8] = {0.f, 0.f, 0.f, 0.f, 0.f, 0.f, 0.f, 0.f};
    const char* Gb = (const char*)G;
    if (valid) {
        uint4 sv = *(const uint4*)(Gb + node * 128 + sub * 16);  // self loop
        acc8(a, sv);
    }
    int j = s0;
    for (; j + 3 < s1; j += 4) {
        int c0 = col[j], c1 = col[j + 1], c2 = col[j + 2], c3 = col[j + 3];
        uint4 v0 = *(const uint4*)(Gb + c0 * 128 + sub * 16);
        uint4 v1 = *(const uint4*)(Gb + c1 * 128 + sub * 16);
        uint4 v2 = *(const uint4*)(Gb + c2 * 128 + sub * 16);
        uint4 v3 = *(const uint4*)(Gb + c3 * 128 + sub * 16);
        acc8(a, v0);
        acc8(a, v1);
        acc8(a, v2);
        acc8(a, v3);
    }
    for (; j < s1; j++) {
        uint4 v = *(const uint4*)(Gb + col[j] * 128 + sub * 16);
        acc8(a, v);
    }
    if (valid) {
        float d = dis[node];
        float4 b0 = *(const float4*)(bias + sub * 8);
        float4 b1 = *(const float4*)(bias + sub * 8 + 4);
        float o0 = fmaf(a[0], d, b0.x);
        float o1 = fmaf(a[1], d, b0.y);
        float o2 = fmaf(a[2], d, b0.z);
        float o3 = fmaf(a[3], d, b0.w);
        float o4 = fmaf(a[4], d, b1.x);
        float o5 = fmaf(a[5], d, b1.y);
        float o6 = fmaf(a[6], d, b1.z);
        float o7 = fmaf(a[7], d, b1.w);
        if (do_relu) {
            o0 = fmaxf(o0, 0.f); o1 = fmaxf(o1, 0.f);
            o2 = fmaxf(o2, 0.f); o3 = fmaxf(o3, 0.f);
            o4 = fmaxf(o4, 0.f); o5 = fmaxf(o5, 0.f);
            o6 = fmaxf(o6, 0.f); o7 = fmaxf(o7, 0.f);
        }
        float* op = outp + node * D + sub * 8;
        *(float4*)op = make_float4(o0, o1, o2, o3);
        *(float4*)(op + 4) = make_float4(o4, o5, o6, o7);
        if (reset_indeg && sub == 0) reset_indeg[node] = 0;
    }
}

// ----------------------------------------------------------------- launch
extern "C" void kernel_launch(void* const* d_in, const int* in_sizes, int n_in,
                              void* d_out, int out_size) {
    const float* x  = (const float*)d_in[0];
    const int*   ei = (const int*)d_in[1];   // int32 (JAX x64 disabled)
    const float* W1 = (const float*)d_in[2];
    const float* b1 = (const float*)d_in[3];
    const float* W2 = (const float*)d_in[4];
    const float* b2 = (const float*)d_in[5];
    float* out = (float*)d_out;

    int N = in_sizes[0] / D;
    int E = in_sizes[1] / 2;
    if (N > MAXN) N = MAXN;
    if (E > MAXE) E = MAXE;
    const int* src = ei;
    const int* dst = ei + E;

    void *p_indeg, *p_rowptr, *p_cursor, *p_col, *p_dis, *p_excl, *p_bsums,
        *p_G, *p_H;
    cudaGetSymbolAddress(&p_indeg, g_indeg);
    cudaGetSymbolAddress(&p_rowptr, g_rowptr);
    cudaGetSymbolAddress(&p_cursor, g_cursor);
    cudaGetSymbolAddress(&p_col, g_col);
    cudaGetSymbolAddress(&p_dis, g_dis);
    cudaGetSymbolAddress(&p_excl, g_excl);
    cudaGetSymbolAddress(&p_bsums, g_bsums);
    cudaGetSymbolAddress(&p_G, g_G);
    cudaGetSymbolAddress(&p_H, g_H);
    int*    indeg  = (int*)p_indeg;
    int*    rowptr = (int*)p_rowptr;
    int*    cursor = (int*)p_cursor;
    int*    col    = (int*)p_col;
    float*  dis    = (float*)p_dis;
    int*    excl   = (int*)p_excl;
    int*    bsums  = (int*)p_bsums;
    __half* G      = (__half*)p_G;
    float*  H      = (float*)p_H;

    int nb = (N + 255) / 256;
    int eb = (E + 255) / 256;
    int sb = (N + 1023) / 1024;
    int gb = (N + 63) / 64;   // 64-row tiles
    int ab = (N + 31) / 32;   // 32 nodes per 256-thread block

    // indeg is zero on entry (zero-init at load; re-zeroed by agg2 each launch)
    k_count<<<eb, 256>>>(dst, indeg, E, N);
    k_scan1<<<sb, 256>>>(indeg, excl, bsums, N);
    k_scan3<<<nb, 256>>>(indeg, excl, bsums, rowptr, cursor, dis, sb, N, E);
    k_fill<<<eb, 256>>>(src, dst, cursor, col, E, N);

    k_gemm<<<gb, 256>>>(x, W1, dis, G, N);
    k_agg<<<ab, 256>>>(rowptr, col, G, dis, b1, H, 1, nullptr, N);
    k_gemm<<<gb, 256>>>(H, W2, dis, G, N);
    k_agg<<<ab, 256>>>(rowptr, col, G, dis, b2, out, 0, indeg, N);
}

// round 7
// speedup vs baseline: 1.6903x; 1.0770x over previous
#include <cuda_runtime.h>
#include <cuda_bf16.h>
#include <cuda_fp16.h>

// GCN: out = GCNConv(relu(GCNConv(x))), symmetric normalization + self loops.
// CSR (dst-indexed) rebuilt per launch; dis folded into GEMM epilogue;
// G stored fp16; fp32 accumulation; no float atomics.
// R7 (= R6 resubmit; infra failure last round):
//   conflict-free GEMM smem (Xs transposed [k][r], pad 68; Wt pad 68,
//   float4 loads both operands); agg unroll-8 (deep gather MLP);
//   int4-vectorized count/fill.

#define MAXN 100000
#define MAXE 1600000
#define D 64

__device__ __align__(16) int    g_indeg[MAXN];
__device__ __align__(16) int    g_rowptr[MAXN + 1];
__device__ __align__(16) int    g_cursor[MAXN];
__device__ __align__(16) int    g_col[MAXE];
__device__ __align__(16) float  g_dis[MAXN];
__device__ __align__(16) int    g_excl[100352];
__device__ __align__(16) int    g_bsums[128];
__device__ __align__(16) __half g_G[MAXN * D];  // fp16 pre-scaled features
__device__ __align__(16) float  g_H[MAXN * D];  // relu output of layer 1

// ---------------------------------------------------------------- degree
// 4 edges per thread (int4), scalar tail.
__global__ void k_count(const int* __restrict__ dst,
                        int* __restrict__ indeg, int E, int N) {
    int t = blockIdx.x * blockDim.x + threadIdx.x;
    int e0 = t * 4;
    if (e0 + 3 < E) {
        int4 d4 = *(const int4*)(dst + e0);
        if (d4.x >= 0 && d4.x < N) atomicAdd(&indeg[d4.x], 1);
        if (d4.y >= 0 && d4.y < N) atomicAdd(&indeg[d4.y], 1);
        if (d4.z >= 0 && d4.z < N) atomicAdd(&indeg[d4.z], 1);
        if (d4.w >= 0 && d4.w < N) atomicAdd(&indeg[d4.w], 1);
    } else {
        for (int e = e0; e < E; e++) {
            int d = dst[e];
            if (d >= 0 && d < N) atomicAdd(&indeg[d], 1);
        }
    }
}

// ------------------------------------------------------------ prefix scan
__global__ void k_scan1(const int* __restrict__ indeg, int* __restrict__ excl,
                        int* __restrict__ bsums, int N) {
    __shared__ int s[256];
    int tid = threadIdx.x;
    int base = blockIdx.x * 1024;
    int v[4];
    int sum = 0;
#pragma unroll
    for (int i = 0; i < 4; i++) {
        int idx = base + tid * 4 + i;
        int x = (idx < N) ? indeg[idx] : 0;
        v[i] = sum;
        sum += x;
    }
    s[tid] = sum;
    __syncthreads();
    for (int off = 1; off < 256; off <<= 1) {
        int t = 0;
        if (tid >= off) t = s[tid - off];
        __syncthreads();
        s[tid] += t;
        __syncthreads();
    }
    int thr_off = s[tid] - sum;
#pragma unroll
    for (int i = 0; i < 4; i++) {
        int idx = base + tid * 4 + i;
        if (idx < N) excl[idx] = thr_off + v[i];
    }
    if (tid == 255) bsums[blockIdx.x] = s[255];
}

// each block (256 nodes) redundantly scans the <=128 chunk sums in smem
__global__ void k_scan3(const int* __restrict__ indeg,
                        const int* __restrict__ excl,
                        const int* __restrict__ bsums,
                        int* __restrict__ rowptr, int* __restrict__ cursor,
                        float* __restrict__ dis, int nb, int N, int E) {
    __shared__ int s[128];
    int tid = threadIdx.x;
    if (tid < 128) s[tid] = (tid < nb) ? bsums[tid] : 0;
    __syncthreads();
    for (int off = 1; off < 128; off <<= 1) {
        int t = 0;
        if (tid < 128 && tid >= off) t = s[tid - off];
        __syncthreads();
        if (tid < 128) s[tid] += t;
        __syncthreads();
    }
    int chunk = (blockIdx.x * 256) >> 10;
    int boff = (chunk > 0) ? s[chunk - 1] : 0;
    int i = blockIdx.x * 256 + tid;
    if (i < N) {
        int e = excl[i] + boff;
        rowptr[i] = e;
        cursor[i] = e;
        dis[i] = rsqrtf((float)(indeg[i] + 1));  // +1 self loop
    }
    if (i == 0) rowptr[N] = E;
}

__global__ void k_fill(const int* __restrict__ src,
                       const int* __restrict__ dst,
                       int* __restrict__ cursor, int* __restrict__ col,
                       int E, int N) {
    int t = blockIdx.x * blockDim.x + threadIdx.x;
    int e0 = t * 4;
    if (e0 + 3 < E) {
        int4 d4 = *(const int4*)(dst + e0);
        int4 s4 = *(const int4*)(src + e0);
        if (d4.x >= 0 && d4.x < N) col[atomicAdd(&cursor[d4.x], 1)] = s4.x;
        if (d4.y >= 0 && d4.y < N) col[atomicAdd(&cursor[d4.y], 1)] = s4.y;
        if (d4.z >= 0 && d4.z < N) col[atomicAdd(&cursor[d4.z], 1)] = s4.z;
        if (d4.w >= 0 && d4.w < N) col[atomicAdd(&cursor[d4.w], 1)] = s4.w;
    } else {
        for (int e = e0; e < E; e++) {
            int d = dst[e];
            if (d >= 0 && d < N) col[atomicAdd(&cursor[d], 1)] = src[e];
        }
    }
}

// ------------------------------------------------------------------ GEMM
// G[n,j] = half( dis[n] * sum_k X[n,k] * W[j,k] ), W row-major [out][in].
// 64x64 tile / block, 256 threads, 4x4 register tile per thread.
// Xs transposed [k][r] (pad 68), Wt [k][j] (pad 68): both operands are
// float4 LDS reads, 2-phase worst case; inner loop is FMA-bound.
__global__ void k_gemm(const float* __restrict__ X, const float* __restrict__ W,
                       const float* __restrict__ dis, __half* __restrict__ G,
                       int N) {
    __shared__ float Xs[64][68];  // [k][r]
    __shared__ float Wt[64][68];  // [k][j]
    int tid = threadIdx.x;
    int base = blockIdx.x * 64;

    for (int idx = tid; idx < 4096; idx += 256) {
        int r = idx >> 6, k = idx & 63;
        int n = base + r;
        Xs[k][r] = (n < N) ? X[n * D + k] : 0.f;  // transpose on store
    }
    for (int idx = tid; idx < 4096; idx += 256) {
        int j = idx >> 6, k = idx & 63;
        Wt[k][j] = W[idx];
    }
    __syncthreads();

    int c4 = (tid & 15) * 4;
    int r4 = (tid >> 4) * 4;
    float acc[4][4];
#pragma unroll
    for (int i = 0; i < 4; i++)
#pragma unroll
        for (int q = 0; q < 4; q++) acc[i][q] = 0.f;

#pragma unroll 8
    for (int k = 0; k < 64; k++) {
        float4 xv = *(const float4*)&Xs[k][r4];
        float4 wv = *(const float4*)&Wt[k][c4];
        acc[0][0] = fmaf(xv.x, wv.x, acc[0][0]);
        acc[0][1] = fmaf(xv.x, wv.y, acc[0][1]);
        acc[0][2] = fmaf(xv.x, wv.z, acc[0][2]);
        acc[0][3] = fmaf(xv.x, wv.w, acc[0][3]);
        acc[1][0] = fmaf(xv.y, wv.x, acc[1][0]);
        acc[1][1] = fmaf(xv.y, wv.y, acc[1][1]);
        acc[1][2] = fmaf(xv.y, wv.z, acc[1][2]);
        acc[1][3] = fmaf(xv.y, wv.w, acc[1][3]);
        acc[2][0] = fmaf(xv.z, wv.x, acc[2][0]);
        acc[2][1] = fmaf(xv.z, wv.y, acc[2][1]);
        acc[2][2] = fmaf(xv.z, wv.z, acc[2][2]);
        acc[2][3] = fmaf(xv.z, wv.w, acc[2][3]);
        acc[3][0] = fmaf(xv.w, wv.x, acc[3][0]);
        acc[3][1] = fmaf(xv.w, wv.y, acc[3][1]);
        acc[3][2] = fmaf(xv.w, wv.z, acc[3][2]);
        acc[3][3] = fmaf(xv.w, wv.w, acc[3][3]);
    }

#pragma unroll
    for (int i = 0; i < 4; i++) {
        int n = base + r4 + i;
        if (n < N) {
            float d = dis[n];
            __half2 h01 = __floats2half2_rn(acc[i][0] * d, acc[i][1] * d);
            __half2 h23 = __floats2half2_rn(acc[i][2] * d, acc[i][3] * d);
            uint2 uu;
            uu.x = *reinterpret_cast<unsigned*>(&h01);
            uu.y = *reinterpret_cast<unsigned*>(&h23);
            *(uint2*)(G + n * D + c4) = uu;
        }
    }
}

// ------------------------------------------------------------- aggregate
// 4 nodes per warp, 8 lanes per node; each lane owns 8 fp16 features (16B).
// Unroll 8: batch col loads, then 8 independent LDG.128 gathers in flight.
__device__ __forceinline__ void acc8(float* a, uint4 v) {
    __half2 h0 = *reinterpret_cast<__half2*>(&v.x);
    __half2 h1 = *reinterpret_cast<__half2*>(&v.y);
    __half2 h2 = *reinterpret_cast<__half2*>(&v.z);
    __half2 h3 = *reinterpret_cast<__half2*>(&v.w);
    float2 f0 = __half22float2(h0);
    float2 f1 = __half22float2(h1);
    float2 f2 = __half22float2(h2);
    float2 f3 = __half22float2(h3);
    a[0] += f0.x; a[1] += f0.y;
    a[2] += f1.x; a[3] += f1.y;
    a[4] += f2.x; a[5] += f2.y;
    a[6] += f3.x; a[7] += f3.y;
}

__global__ void k_agg(const int* __restrict__ rowptr,
                      const int* __restrict__ col,
                      const __half* __restrict__ G,
                      const float* __restrict__ dis,
                      const float* __restrict__ bias,
                      float* __restrict__ outp, int do_relu,
                      int* reset_indeg, int N) {
    int gw = (blockIdx.x * blockDim.x + threadIdx.x) >> 5;
    int lane = threadIdx.x & 31;
    int node = gw * 4 + (lane >> 3);
    int sub = lane & 7;
    bool valid = node < N;
    int s0 = 0, s1 = 0;
    if (valid) {
        s0 = rowptr[node];
        s1 = rowptr[node + 1];
    }
    float a[8] = {0.f, 0.f, 0.f, 0.f, 0.f, 0.f, 0.f, 0.f};
    const char* Gs = (const char*)G + sub * 16;
    if (valid) {
        uint4 sv = *(const uint4*)(Gs + (size_t)node * 128);  // self loop
        acc8(a, sv);
    }
    int j = s0;
    for (; j + 7 < s1; j += 8) {
        int c0 = col[j],     c1 = col[j + 1], c2 = col[j + 2], c3 = col[j + 3];
        int c4 = col[j + 4], c5 = col[j + 5], c6 = col[j + 6], c7 = col[j + 7];
        uint4 v0 = *(const uint4*)(Gs + (size_t)c0 * 128);
        uint4 v1 = *(const uint4*)(Gs + (size_t)c1 * 128);
        uint4 v2 = *(const uint4*)(Gs + (size_t)c2 * 128);
        uint4 v3 = *(const uint4*)(Gs + (size_t)c3 * 128);
        uint4 v4 = *(const uint4*)(Gs + (size_t)c4 * 128);
        uint4 v5 = *(const uint4*)(Gs + (size_t)c5 * 128);
        uint4 v6 = *(const uint4*)(Gs + (size_t)c6 * 128);
        uint4 v7 = *(const uint4*)(Gs + (size_t)c7 * 128);
        acc8(a, v0); acc8(a, v1); acc8(a, v2); acc8(a, v3);
        acc8(a, v4); acc8(a, v5); acc8(a, v6); acc8(a, v7);
    }
    for (; j + 1 < s1; j += 2) {
        int c0 = col[j], c1 = col[j + 1];
        uint4 v0 = *(const uint4*)(Gs + (size_t)c0 * 128);
        uint4 v1 = *(const uint4*)(Gs + (size_t)c1 * 128);
        acc8(a, v0); acc8(a, v1);
    }
    if (j < s1) {
        uint4 v = *(const uint4*)(Gs + (size_t)col[j] * 128);
        acc8(a, v);
    }
    if (valid) {
        float d = dis[node];
        float4 b0 = *(const float4*)(bias + sub * 8);
        float4 b1 = *(const float4*)(bias + sub * 8 + 4);
        float o0 = fmaf(a[0], d, b0.x);
        float o1 = fmaf(a[1], d, b0.y);
        float o2 = fmaf(a[2], d, b0.z);
        float o3 = fmaf(a[3], d, b0.w);
        float o4 = fmaf(a[4], d, b1.x);
        float o5 = fmaf(a[5], d, b1.y);
        float o6 = fmaf(a[6], d, b1.z);
        float o7 = fmaf(a[7], d, b1.w);
        if (do_relu) {
            o0 = fmaxf(o0, 0.f); o1 = fmaxf(o1, 0.f);
            o2 = fmaxf(o2, 0.f); o3 = fmaxf(o3, 0.f);
            o4 = fmaxf(o4, 0.f); o5 = fmaxf(o5, 0.f);
            o6 = fmaxf(o6, 0.f); o7 = fmaxf(o7, 0.f);
        }
        float* op = outp + node * D + sub * 8;
        *(float4*)op = make_float4(o0, o1, o2, o3);
        *(float4*)(op + 4) = make_float4(o4, o5, o6, o7);
        if (reset_indeg && sub == 0) reset_indeg[node] = 0;
    }
}

// ----------------------------------------------------------------- launch
extern "C" void kernel_launch(void* const* d_in, const int* in_sizes, int n_in,
                              void* d_out, int out_size) {
    const float* x  = (const float*)d_in[0];
    const int*   ei = (const int*)d_in[1];   // int32 (JAX x64 disabled)
    const float* W1 = (const float*)d_in[2];
    const float* b1 = (const float*)d_in[3];
    const float* W2 = (const float*)d_in[4];
    const float* b2 = (const float*)d_in[5];
    float* out = (float*)d_out;

    int N = in_sizes[0] / D;
    int E = in_sizes[1] / 2;
    if (N > MAXN) N = MAXN;
    if (E > MAXE) E = MAXE;
    const int* src = ei;
    const int* dst = ei + E;

    void *p_indeg, *p_rowptr, *p_cursor, *p_col, *p_dis, *p_excl, *p_bsums,
        *p_G, *p_H;
    cudaGetSymbolAddress(&p_indeg, g_indeg);
    cudaGetSymbolAddress(&p_rowptr, g_rowptr);
    cudaGetSymbolAddress(&p_cursor, g_cursor);
    cudaGetSymbolAddress(&p_col, g_col);
    cudaGetSymbolAddress(&p_dis, g_dis);
    cudaGetSymbolAddress(&p_excl, g_excl);
    cudaGetSymbolAddress(&p_bsums, g_bsums);
    cudaGetSymbolAddress(&p_G, g_G);
    cudaGetSymbolAddress(&p_H, g_H);
    int*    indeg  = (int*)p_indeg;
    int*    rowptr = (int*)p_rowptr;
    int*    cursor = (int*)p_cursor;
    int*    col    = (int*)p_col;
    float*  dis    = (float*)p_dis;
    int*    excl   = (int*)p_excl;
    int*    bsums  = (int*)p_bsums;
    __half* G      = (__half*)p_G;
    float*  H      = (float*)p_H;

    int nb = (N + 255) / 256;
    int e4 = (E + 3) / 4;               // 4 edges per thread
    int eb = (e4 + 255) / 256;
    int sb = (N + 1023) / 1024;
    int gb = (N + 63) / 64;             // 64-row tiles
    int ab = (N + 31) / 32;             // 32 nodes per 256-thread block

    // indeg is zero on entry (zero-init at load; re-zeroed by agg2 each launch)
    k_count<<<eb, 256>>>(dst, indeg, E, N);
    k_scan1<<<sb, 256>>>(indeg, excl, bsums, N);
    k_scan3<<<nb, 256>>>(indeg, excl, bsums, rowptr, cursor, dis, sb, N, E);
    k_fill<<<eb, 256>>>(src, dst, cursor, col, E, N);

    k_gemm<<<gb, 256>>>(x, W1, dis, G, N);
    k_agg<<<ab, 256>>>(rowptr, col, G, dis, b1, H, 1, nullptr, N);
    k_gemm<<<gb, 256>>>(H, W2, dis, G, N);
    k_agg<<<ab, 256>>>(rowptr, col, G, dis, b2, out, 0, indeg, N);
}